// round 4
// baseline (speedup 1.0000x reference)
#include <cuda_runtime.h>
#include <math.h>

#define NROWS 32768
#define BITS  64
#define MDIM  8
#define SUBD  8
#define HID   256
#define NCLS  100
#define TS    64
#define NTX   512
#define KC    8

__device__ float              g_xp[NROWS*BITS];
__device__ unsigned long long g_flipmap[NROWS];
__device__ unsigned long long g_targ[NROWS];
__device__ unsigned long long g_yb[NROWS*2];
__device__ int                g_cnt[NROWS];
__device__ unsigned long long g_cbits[NCLS];
__device__ uint2              g_kmap, g_kraw;
__device__ double             g_partLoss[2*4096];
__device__ unsigned           g_partHits[4096];
__device__ unsigned long long g_partDist[4096];
__device__ unsigned long long g_partCnt[4096];

// ---------------- threefry2x32 (JAX-exact) ----------------
__device__ __forceinline__ void tf2x32(unsigned k0, unsigned k1, unsigned x0, unsigned x1,
                                       unsigned &o0, unsigned &o1) {
    unsigned ks2 = k0 ^ k1 ^ 0x1BD11BDAu;
    x0 += k0; x1 += k1;
#define TFR(r) { x0 += x1; x1 = (x1<<(r))|(x1>>(32-(r))); x1 ^= x0; }
    TFR(13) TFR(15) TFR(26) TFR(6)   x0 += k1;  x1 += ks2 + 1u;
    TFR(17) TFR(29) TFR(16) TFR(24)  x0 += ks2; x1 += k0  + 2u;
    TFR(13) TFR(15) TFR(26) TFR(6)   x0 += k0;  x1 += k1  + 3u;
    TFR(17) TFR(29) TFR(16) TFR(24)  x0 += k1;  x1 += ks2 + 4u;
    TFR(13) TFR(15) TFR(26) TFR(6)   x0 += ks2; x1 += k0  + 5u;
#undef TFR
    o0 = x0; o1 = x1;
}
__device__ __forceinline__ unsigned rbits32(uint2 key, unsigned i) {
    unsigned a, b; tf2x32(key.x, key.y, 0u, i, a, b); return a ^ b;
}

// flipped positions = { rank(rand[t]) : template[t] }, stable tie-break by index
__device__ unsigned long long warp_flipmask(uint2 key, int n, int lane, const int* __restrict__ tmpl) {
    unsigned r0 = rbits32(key, (unsigned)(n*BITS + lane));
    unsigned r1 = rbits32(key, (unsigned)(n*BITS + lane + 32));
    unsigned K0 = ((r0 >> 9) << 6) | (unsigned)lane;
    unsigned K1 = ((r1 >> 9) << 6) | (unsigned)(lane + 32);
    unsigned t0 = __ballot_sync(0xffffffffu, tmpl[lane]      != 0);
    unsigned t1 = __ballot_sync(0xffffffffu, tmpl[lane + 32] != 0);
    unsigned long long flip = 0ull;
    unsigned mm = t0;
    while (mm) {
        int t = __ffs(mm) - 1; mm &= mm - 1;
        unsigned Kt = __shfl_sync(0xffffffffu, K0, t);
        int rank = __popc(__ballot_sync(0xffffffffu, K0 < Kt))
                 + __popc(__ballot_sync(0xffffffffu, K1 < Kt));
        flip |= 1ull << rank;
    }
    mm = t1;
    while (mm) {
        int t = __ffs(mm) - 1; mm &= mm - 1;
        unsigned Kt = __shfl_sync(0xffffffffu, K1, t);
        int rank = __popc(__ballot_sync(0xffffffffu, K0 < Kt))
                 + __popc(__ballot_sync(0xffffffffu, K1 < Kt));
        flip |= 1ull << rank;
    }
    return flip;
}

__global__ void k_init(const float* __restrict__ cen, const int* __restrict__ perm) {
    int t = threadIdx.x;
    if (t == 0) {
        unsigned a, b;
        tf2x32(0u, 1u, 0u, 0u, a, b); g_kmap = make_uint2(a, b);
        tf2x32(0u, 1u, 0u, 1u, a, b); g_kraw = make_uint2(a, b);
    }
    if (t < NCLS) {
        unsigned long long bits = 0ull;
        for (int k = 0; k < BITS; k++)
            if (cen[t*BITS + perm[k]] > 0.f) bits |= 1ull << k;
        g_cbits[t] = bits;
    }
}

__global__ void k_rows(const float* __restrict__ x, const int* __restrict__ y,
                       const int* __restrict__ perm,
                       const int* __restrict__ tmap, const int* __restrict__ traw) {
    __shared__ int perm_s[BITS];
    __shared__ unsigned long long cb_s[NCLS];
    __shared__ unsigned wdist[8], wcnt[8];
    const int tid = threadIdx.x, lane = tid & 31, w = tid >> 5;
    if (tid < BITS) perm_s[tid] = perm[tid];
    if (tid < NCLS) cb_s[tid] = g_cbits[tid];
    __syncthreads();

    const int n = blockIdx.x * 8 + w;
    const int c0 = lane, c1 = lane + 32;
    float v0 = x[n*BITS + perm_s[c0]];
    float v1 = x[n*BITS + perm_s[c1]];
    g_xp[n*BITS + c0] = v0;
    g_xp[n*BITS + c1] = v1;

    g_flipmap[n] = warp_flipmask(g_kmap, n, lane, tmap);
    unsigned long long frawm = warp_flipmask(g_kraw, n, lane, traw);

    bool bit0 = ((frawm >> c0) & 1ull) ? (v0 < 0.f) : (v0 > 0.f);
    bool bit1 = ((frawm >> c1) & 1ull) ? (v1 < 0.f) : (v1 > 0.f);
    unsigned lo = __ballot_sync(0xffffffffu, bit0);
    unsigned hi = __ballot_sync(0xffffffffu, bit1);
    g_targ[n] = (unsigned long long)lo | ((unsigned long long)hi << 32);

    lo = __ballot_sync(0xffffffffu, v0 > 0.f);
    hi = __ballot_sync(0xffffffffu, v1 > 0.f);
    unsigned long long cx = (unsigned long long)lo | ((unsigned long long)hi << 32);

    const int* yr = y + n*NCLS;
    unsigned bal[4]; unsigned mydist = 0;
#pragma unroll
    for (int q = 0; q < 4; q++) {
        int c = lane + 32*q;
        bool a = (c < NCLS) ? (yr[c] > 0) : false;
        bal[q] = __ballot_sync(0xffffffffu, a);
        if (a) mydist += (unsigned)__popcll(cx ^ cb_s[c]);
    }
    unsigned long long yb0 = (unsigned long long)bal[0] | ((unsigned long long)bal[1] << 32);
    unsigned long long yb1 = (unsigned long long)bal[2] | ((unsigned long long)bal[3] << 32);
    int cnt = __popcll(yb0) + __popcll(yb1);
    if (lane == 0) { g_yb[2*n] = yb0; g_yb[2*n+1] = yb1; g_cnt[n] = cnt; }

    for (int o = 16; o; o >>= 1) mydist += __shfl_down_sync(0xffffffffu, mydist, o);
    if (lane == 0) { wdist[w] = mydist; wcnt[w] = (unsigned)cnt; }
    __syncthreads();
    if (tid == 0) {
        unsigned D = 0, C = 0;
        for (int i = 0; i < 8; i++) { D += wdist[i]; C += wcnt[i]; }
        g_partDist[blockIdx.x] = D;
        g_partCnt[blockIdx.x] = C;
    }
}

__device__ __forceinline__ void fma2(float2 &d, float2 a, float2 b) {
    asm("fma.rn.f32x2 %0, %1, %2, %0;"
        : "+l"(reinterpret_cast<unsigned long long&>(d))
        : "l"(reinterpret_cast<unsigned long long&>(a)),
          "l"(reinterpret_cast<unsigned long long&>(b)));
}

#define SM_HP 0
#define SM_W2 65536
#define SM_XS 81920
#define SM_FM 83968
#define SM_CT 84480
#define SM_RL 84896
#define SM_RH 84960
#define SMEM_BYTES 85504

__global__ void __launch_bounds__(256)
k_gemm(const float* __restrict__ W1, const float* __restrict__ b1,
       const float* __restrict__ W2, const float* __restrict__ b2) {
    extern __shared__ char smem[];
    float2* hp  = (float2*)(smem + SM_HP);
    float2* w2s = (float2*)(smem + SM_W2);
    float*  xs  = (float*) (smem + SM_XS);
    unsigned long long* fm = (unsigned long long*)(smem + SM_FM);
    int*    ctm = (int*)   (smem + SM_CT);
    double* redL = (double*)(smem + SM_RL);
    unsigned* redH = (unsigned*)(smem + SM_RH);

    const int tid = threadIdx.x, lane = tid & 31, w = tid >> 5;
    const int m = blockIdx.y, pass = blockIdx.z;
    const int s0 = blockIdx.x * TS;

    if (pass == 1) { if (tid < TS) fm[tid] = g_flipmap[s0 + tid]; }
    else           { if (tid < NCLS) ctm[tid] = (int)((g_cbits[tid] >> (8*m)) & 0xFFull); }
    for (int i = tid; i < TS*SUBD; i += 256) {
        int s = i >> 3, k = i & 7;
        xs[i] = g_xp[(s0 + s)*BITS + m*SUBD + k];
    }
    __syncthreads();
    if (pass == 1) {
        for (int i = tid; i < TS*SUBD; i += 256) {
            int s = i >> 3, k = i & 7;
            if ((fm[s] >> (m*SUBD + k)) & 1ull) xs[i] = -xs[i];
        }
        __syncthreads();
    }

    // first layer: thread = hidden unit, loop over 64 samples
    float w1r[SUBD];
#pragma unroll
    for (int k = 0; k < SUBD; k++) w1r[k] = W1[(m*SUBD + k)*HID + tid];
    const float b1v = b1[m*HID + tid];
    float he = 0.f;
    for (int s = 0; s < TS; s++) {
        float pre = b1v;
#pragma unroll
        for (int k = 0; k < SUBD; k++) pre += xs[s*SUBD + k] * w1r[k];
        float hv = pre / (1.f + expf(-pre));
        if (s & 1) hp[(s >> 1)*HID + tid] = make_float2(he, hv);
        else       he = hv;
    }

    // second layer: 64x256x256, f32x2 packed (2 samples/FMA)
    float2 acc[4][8];
#pragma unroll
    for (int j = 0; j < 8; j++) {
        float bv = b2[m*HID + lane + 32*j];
#pragma unroll
        for (int p = 0; p < 4; p++) acc[p][j] = make_float2(bv, bv);
    }
    const float* W2m = W2 + m*HID*HID;
    for (int k0 = 0; k0 < HID; k0 += KC) {
        __syncthreads();
#pragma unroll
        for (int q = 0; q < KC; q++) {
            float v = W2m[(k0 + q)*HID + tid];
            w2s[q*HID + tid] = make_float2(v, v);
        }
        __syncthreads();
#pragma unroll
        for (int i = 0; i < KC; i++) {
            float2 hv[4];
#pragma unroll
            for (int p = 0; p < 4; p++) hv[p] = hp[(w*4 + p)*HID + (k0 + i)];
#pragma unroll
            for (int j = 0; j < 8; j++) {
                float2 wv = w2s[i*HID + lane + 32*j];
#pragma unroll
                for (int p = 0; p < 4; p++) fma2(acc[p][j], hv[p], wv);
            }
        }
    }

    __syncthreads();
    float* lg = (float*)(smem + SM_HP);
#pragma unroll
    for (int p = 0; p < 4; p++) {
        int s = (w*4 + p)*2;
#pragma unroll
        for (int j = 0; j < 8; j++) {
            int c = lane + 32*j;
            lg[s*HID + c]     = acc[p][j].x;
            lg[(s+1)*HID + c] = acc[p][j].y;
        }
    }
    __syncthreads();

    // epilogue: warp w -> samples w*8..w*8+7
    double lossSum = 0.0; unsigned hitSum = 0;
    for (int si = 0; si < 8; si++) {
        int s = w*8 + si, n = s0 + s;
        float v[8];
#pragma unroll
        for (int j = 0; j < 8; j++) v[j] = lg[s*HID + lane + 32*j];
        float mx = v[0]; int ai = lane;
#pragma unroll
        for (int j = 1; j < 8; j++) if (v[j] > mx) { mx = v[j]; ai = lane + 32*j; }
        for (int o = 16; o; o >>= 1) {
            float omx = __shfl_down_sync(0xffffffffu, mx, o);
            int   oai = __shfl_down_sync(0xffffffffu, ai, o);
            if (omx > mx || (omx == mx && oai < ai)) { mx = omx; ai = oai; }
        }
        mx = __shfl_sync(0xffffffffu, mx, 0);
        ai = __shfl_sync(0xffffffffu, ai, 0);
        float se = 0.f;
#pragma unroll
        for (int j = 0; j < 8; j++) se += expf(v[j] - mx);
        for (int o = 16; o; o >>= 1) se += __shfl_xor_sync(0xffffffffu, se, o);
        float lse = mx + logf(se);
        if (pass == 1) {
            int t = (int)((g_targ[n] >> (8*m)) & 0xFFull);
            float picked = lg[s*HID + t];
            if (lane == 0) { lossSum += (double)(lse - picked); hitSum += (ai == t) ? 1u : 0u; }
        } else {
            unsigned long long yb0 = g_yb[2*n], yb1 = g_yb[2*n+1];
            int cnt = g_cnt[n];
            float ps = 0.f;
#pragma unroll
            for (int q = 0; q < 4; q++) {
                int c = lane + 32*q;
                if (c < NCLS) {
                    bool act = (((c < 64) ? (yb0 >> c) : (yb1 >> (c - 64))) & 1ull) != 0;
                    if (act) ps += lg[s*HID + ctm[c]];
                }
            }
            for (int o = 16; o; o >>= 1) ps += __shfl_xor_sync(0xffffffffu, ps, o);
            if (lane == 0) lossSum += (double)(lse - ps / (float)cnt);
        }
    }
    if (lane == 0) { redL[w] = lossSum; redH[w] = hitSum; }
    __syncthreads();
    if (tid == 0) {
        double L = 0; unsigned H = 0;
        for (int i = 0; i < 8; i++) { L += redL[i]; H += redH[i]; }
        g_partLoss[pass*4096 + m*512 + blockIdx.x] = L;
        if (pass == 1) g_partHits[m*512 + blockIdx.x] = H;
    }
}

__global__ void k_final(float* out) {
    __shared__ double sL0[256], sL1[256], sD[256], sC[256];
    __shared__ unsigned long long sH[256];
    int t = threadIdx.x;
    double l0 = 0, l1 = 0, dd = 0, cc = 0; unsigned long long hh = 0;
    for (int i = t; i < 4096; i += 256) {
        l0 += g_partLoss[i];
        l1 += g_partLoss[4096 + i];
        hh += g_partHits[i];
        dd += (double)g_partDist[i];
        cc += (double)g_partCnt[i];
    }
    sL0[t] = l0; sL1[t] = l1; sD[t] = dd; sC[t] = cc; sH[t] = hh;
    __syncthreads();
    if (t == 0) {
        double L0 = 0, L1 = 0, D = 0, C = 0; unsigned long long H = 0;
        for (int i = 0; i < 256; i++) { L0 += sL0[i]; L1 += sL1[i]; D += sD[i]; C += sC[i]; H += sH[i]; }
        double net = L0 / NROWS, map = L1 / NROWS;
        out[0] = (float)(net + map);
        out[1] = (float)net;
        out[2] = (float)map;
        out[3] = (float)((double)H / (double)(NROWS * MDIM));
        out[4] = (float)(D / C);
    }
}

extern "C" void kernel_launch(void* const* d_in, const int* in_sizes, int n_in,
                              void* d_out, int out_size) {
    const float *x = 0, *cen = 0, *W1 = 0, *b1 = 0, *W2 = 0, *b2 = 0;
    const int *y = 0, *perm = 0, *tmap = 0, *traw = 0;
    int n64 = 0, n2048 = 0;
    for (int i = 0; i < n_in; i++) {
        int s = in_sizes[i];
        if      (s == NROWS*BITS)     x   = (const float*)d_in[i];
        else if (s == NROWS*NCLS)     y   = (const int*)d_in[i];
        else if (s == NCLS*BITS)      cen = (const float*)d_in[i];
        else if (s == MDIM*SUBD*HID)  W1  = (const float*)d_in[i];
        else if (s == MDIM*HID*HID)   W2  = (const float*)d_in[i];
        else if (s == MDIM*HID) { if (n2048++ == 0) b1 = (const float*)d_in[i]; else b2 = (const float*)d_in[i]; }
        else if (s == BITS) {
            if (n64 == 0)      perm = (const int*)d_in[i];
            else if (n64 == 1) tmap = (const int*)d_in[i];
            else               traw = (const int*)d_in[i];
            n64++;
        }
    }
    cudaFuncSetAttribute(k_gemm, cudaFuncAttributeMaxDynamicSharedMemorySize, SMEM_BYTES);
    k_init<<<1, 128>>>(cen, perm);
    k_rows<<<4096, 256>>>(x, y, perm, tmap, traw);
    k_gemm<<<dim3(NTX, MDIM, 2), 256, SMEM_BYTES>>>(W1, b1, W2, b2);
    k_final<<<1, 256>>>((float*)d_out);
}

// round 6
// speedup vs baseline: 1.0670x; 1.0670x over previous
#include <cuda_runtime.h>
#include <math.h>

#define NROWS 32768
#define BITS  64
#define MDIM  8
#define SUBD  8
#define HID   256
#define NCLS  100
#define TS    64
#define NTX   512
#define KC    16

__device__ float              g_xp[NROWS*BITS];
__device__ unsigned long long g_flipmap[NROWS];
__device__ unsigned long long g_targ[NROWS];
__device__ unsigned long long g_yb[NROWS*2];
__device__ int                g_cnt[NROWS];
__device__ unsigned long long g_cbits[NCLS];
__device__ uint2              g_kmap, g_kraw;
__device__ double             g_partLoss[2*4096];
__device__ unsigned           g_partHits[4096];
__device__ unsigned long long g_partDist[4096];
__device__ unsigned long long g_partCnt[4096];

// ---------------- threefry2x32 (JAX-exact) ----------------
__device__ __forceinline__ void tf2x32(unsigned k0, unsigned k1, unsigned x0, unsigned x1,
                                       unsigned &o0, unsigned &o1) {
    unsigned ks2 = k0 ^ k1 ^ 0x1BD11BDAu;
    x0 += k0; x1 += k1;
#define TFR(r) { x0 += x1; x1 = (x1<<(r))|(x1>>(32-(r))); x1 ^= x0; }
    TFR(13) TFR(15) TFR(26) TFR(6)   x0 += k1;  x1 += ks2 + 1u;
    TFR(17) TFR(29) TFR(16) TFR(24)  x0 += ks2; x1 += k0  + 2u;
    TFR(13) TFR(15) TFR(26) TFR(6)   x0 += k0;  x1 += k1  + 3u;
    TFR(17) TFR(29) TFR(16) TFR(24)  x0 += k1;  x1 += ks2 + 4u;
    TFR(13) TFR(15) TFR(26) TFR(6)   x0 += ks2; x1 += k0  + 5u;
#undef TFR
    o0 = x0; o1 = x1;
}
__device__ __forceinline__ unsigned rbits32(uint2 key, unsigned i) {
    unsigned a, b; tf2x32(key.x, key.y, 0u, i, a, b); return a ^ b;
}

__device__ unsigned long long warp_flipmask(uint2 key, int n, int lane, const int* __restrict__ tmpl) {
    unsigned r0 = rbits32(key, (unsigned)(n*BITS + lane));
    unsigned r1 = rbits32(key, (unsigned)(n*BITS + lane + 32));
    unsigned K0 = ((r0 >> 9) << 6) | (unsigned)lane;
    unsigned K1 = ((r1 >> 9) << 6) | (unsigned)(lane + 32);
    unsigned t0 = __ballot_sync(0xffffffffu, tmpl[lane]      != 0);
    unsigned t1 = __ballot_sync(0xffffffffu, tmpl[lane + 32] != 0);
    unsigned long long flip = 0ull;
    unsigned mm = t0;
    while (mm) {
        int t = __ffs(mm) - 1; mm &= mm - 1;
        unsigned Kt = __shfl_sync(0xffffffffu, K0, t);
        int rank = __popc(__ballot_sync(0xffffffffu, K0 < Kt))
                 + __popc(__ballot_sync(0xffffffffu, K1 < Kt));
        flip |= 1ull << rank;
    }
    mm = t1;
    while (mm) {
        int t = __ffs(mm) - 1; mm &= mm - 1;
        unsigned Kt = __shfl_sync(0xffffffffu, K1, t);
        int rank = __popc(__ballot_sync(0xffffffffu, K0 < Kt))
                 + __popc(__ballot_sync(0xffffffffu, K1 < Kt));
        flip |= 1ull << rank;
    }
    return flip;
}

__global__ void k_init(const float* __restrict__ cen, const int* __restrict__ perm) {
    int t = threadIdx.x;
    if (t == 0) {
        unsigned a, b;
        tf2x32(0u, 1u, 0u, 0u, a, b); g_kmap = make_uint2(a, b);
        tf2x32(0u, 1u, 0u, 1u, a, b); g_kraw = make_uint2(a, b);
    }
    if (t < NCLS) {
        unsigned long long bits = 0ull;
        for (int k = 0; k < BITS; k++)
            if (cen[t*BITS + perm[k]] > 0.f) bits |= 1ull << k;
        g_cbits[t] = bits;
    }
}

__global__ void k_rows(const float* __restrict__ x, const int* __restrict__ y,
                       const int* __restrict__ perm,
                       const int* __restrict__ tmap, const int* __restrict__ traw) {
    __shared__ int perm_s[BITS];
    __shared__ unsigned long long cb_s[NCLS];
    __shared__ unsigned wdist[8], wcnt[8];
    const int tid = threadIdx.x, lane = tid & 31, w = tid >> 5;
    if (tid < BITS) perm_s[tid] = perm[tid];
    if (tid < NCLS) cb_s[tid] = g_cbits[tid];
    __syncthreads();

    const int n = blockIdx.x * 8 + w;
    const int c0 = lane, c1 = lane + 32;
    float v0 = x[n*BITS + perm_s[c0]];
    float v1 = x[n*BITS + perm_s[c1]];
    g_xp[n*BITS + c0] = v0;
    g_xp[n*BITS + c1] = v1;

    g_flipmap[n] = warp_flipmask(g_kmap, n, lane, tmap);
    unsigned long long frawm = warp_flipmask(g_kraw, n, lane, traw);

    bool bit0 = ((frawm >> c0) & 1ull) ? (v0 < 0.f) : (v0 > 0.f);
    bool bit1 = ((frawm >> c1) & 1ull) ? (v1 < 0.f) : (v1 > 0.f);
    unsigned lo = __ballot_sync(0xffffffffu, bit0);
    unsigned hi = __ballot_sync(0xffffffffu, bit1);
    g_targ[n] = (unsigned long long)lo | ((unsigned long long)hi << 32);

    lo = __ballot_sync(0xffffffffu, v0 > 0.f);
    hi = __ballot_sync(0xffffffffu, v1 > 0.f);
    unsigned long long cx = (unsigned long long)lo | ((unsigned long long)hi << 32);

    const int* yr = y + n*NCLS;
    unsigned bal[4]; unsigned mydist = 0;
#pragma unroll
    for (int q = 0; q < 4; q++) {
        int c = lane + 32*q;
        bool a = (c < NCLS) ? (yr[c] > 0) : false;
        bal[q] = __ballot_sync(0xffffffffu, a);
        if (a) mydist += (unsigned)__popcll(cx ^ cb_s[c]);
    }
    unsigned long long yb0 = (unsigned long long)bal[0] | ((unsigned long long)bal[1] << 32);
    unsigned long long yb1 = (unsigned long long)bal[2] | ((unsigned long long)bal[3] << 32);
    int cnt = __popcll(yb0) + __popcll(yb1);
    if (lane == 0) { g_yb[2*n] = yb0; g_yb[2*n+1] = yb1; g_cnt[n] = cnt; }

    for (int o = 16; o; o >>= 1) mydist += __shfl_down_sync(0xffffffffu, mydist, o);
    if (lane == 0) { wdist[w] = mydist; wcnt[w] = (unsigned)cnt; }
    __syncthreads();
    if (tid == 0) {
        unsigned D = 0, C = 0;
        for (int i = 0; i < 8; i++) { D += wdist[i]; C += wcnt[i]; }
        g_partDist[blockIdx.x] = D;
        g_partCnt[blockIdx.x] = C;
    }
}

__device__ __forceinline__ void fma2(float2 &d, float2 a, float2 b) {
    asm("fma.rn.f32x2 %0, %1, %2, %0;"
        : "+l"(reinterpret_cast<unsigned long long&>(d))
        : "l"(reinterpret_cast<unsigned long long&>(a)),
          "l"(reinterpret_cast<unsigned long long&>(b)));
}

#define SM_HP 0
#define SM_W2 65536
#define SM_XS 98304
#define SM_FM 100352
#define SM_CT 100864
#define SM_RL 101376
#define SM_RH 101440
#define SMEM_BYTES 101504

__global__ void __launch_bounds__(256, 2)
k_gemm(const float* __restrict__ W1, const float* __restrict__ b1,
       const float* __restrict__ W2, const float* __restrict__ b2) {
    extern __shared__ char smem[];
    float2* hp  = (float2*)(smem + SM_HP);
    float2* w2s = (float2*)(smem + SM_W2);
    float*  xs  = (float*) (smem + SM_XS);
    unsigned long long* fm = (unsigned long long*)(smem + SM_FM);
    int*    ctm = (int*)   (smem + SM_CT);
    double* redL = (double*)(smem + SM_RL);
    unsigned* redH = (unsigned*)(smem + SM_RH);

    const int tid = threadIdx.x, lane = tid & 31, w = tid >> 5;
    const int sg = w >> 1, cg = w & 1;           // warp tile: 16 samples x 128 cols
    const int m = blockIdx.y, pass = blockIdx.z;
    const int s0 = blockIdx.x * TS;

    if (pass == 1) { if (tid < TS) fm[tid] = g_flipmap[s0 + tid]; }
    else           { if (tid < NCLS) ctm[tid] = (int)((g_cbits[tid] >> (8*m)) & 0xFFull); }
    for (int i = tid; i < TS*SUBD; i += 256) {
        int s = i >> 3, k = i & 7;
        xs[i] = g_xp[(s0 + s)*BITS + m*SUBD + k];
    }
    __syncthreads();
    if (pass == 1) {
        for (int i = tid; i < TS*SUBD; i += 256) {
            int s = i >> 3, k = i & 7;
            if ((fm[s] >> (m*SUBD + k)) & 1ull) xs[i] = -xs[i];
        }
        __syncthreads();
    }

    // first layer: thread = hidden unit (col tid), loop over 64 samples; pack sample pairs
    float w1r[SUBD];
#pragma unroll
    for (int k = 0; k < SUBD; k++) w1r[k] = W1[(m*SUBD + k)*HID + tid];
    const float b1v = b1[m*HID + tid];
    float he = 0.f;
    for (int s = 0; s < TS; s++) {
        float pre = b1v;
#pragma unroll
        for (int k = 0; k < SUBD; k++) pre += xs[s*SUBD + k] * w1r[k];
        float hv = pre / (1.f + expf(-pre));
        if (s & 1) hp[(s >> 1)*HID + tid] = make_float2(he, hv);
        else       he = hv;
    }

    // second layer: warp computes 16 samples (8 pairs) x 128 cols (4 cols/lane)
    float2 acc[8][4];
#pragma unroll
    for (int j = 0; j < 4; j++) {
        float bv = b2[m*HID + cg*128 + lane + 32*j];
#pragma unroll
        for (int p = 0; p < 8; p++) acc[p][j] = make_float2(bv, bv);
    }
    const float* W2m = W2 + m*HID*HID;
    for (int k0 = 0; k0 < HID; k0 += KC) {
        __syncthreads();
#pragma unroll
        for (int q = 0; q < KC; q++) {
            float v = W2m[(k0 + q)*HID + tid];
            w2s[q*HID + tid] = make_float2(v, v);
        }
        __syncthreads();
#pragma unroll
        for (int kk = 0; kk < KC; kk += 2) {
            float4 hv[8];
#pragma unroll
            for (int p = 0; p < 8; p++)
                hv[p] = *(const float4*)&hp[(sg*8 + p)*HID + k0 + kk];
#pragma unroll
            for (int j = 0; j < 4; j++) {
                float2 wv0 = w2s[kk*HID + cg*128 + lane + 32*j];
                float2 wv1 = w2s[(kk+1)*HID + cg*128 + lane + 32*j];
#pragma unroll
                for (int p = 0; p < 8; p++) {
                    fma2(acc[p][j], make_float2(hv[p].x, hv[p].y), wv0);
                    fma2(acc[p][j], make_float2(hv[p].z, hv[p].w), wv1);
                }
            }
        }
    }

    __syncthreads();
    float* lg = (float*)(smem + SM_HP);
#pragma unroll
    for (int p = 0; p < 8; p++) {
        int s = sg*16 + 2*p;
#pragma unroll
        for (int j = 0; j < 4; j++) {
            int c = cg*128 + lane + 32*j;
            lg[s*HID + c]     = acc[p][j].x;
            lg[(s+1)*HID + c] = acc[p][j].y;
        }
    }
    __syncthreads();

    // epilogue: warp w -> samples w*8..w*8+7
    double lossSum = 0.0; unsigned hitSum = 0;
    for (int si = 0; si < 8; si++) {
        int s = w*8 + si, n = s0 + s;
        float v[8];
#pragma unroll
        for (int j = 0; j < 8; j++) v[j] = lg[s*HID + lane + 32*j];
        float mx = v[0]; int ai = lane;
#pragma unroll
        for (int j = 1; j < 8; j++) if (v[j] > mx) { mx = v[j]; ai = lane + 32*j; }
        for (int o = 16; o; o >>= 1) {
            float omx = __shfl_down_sync(0xffffffffu, mx, o);
            int   oai = __shfl_down_sync(0xffffffffu, ai, o);
            if (omx > mx || (omx == mx && oai < ai)) { mx = omx; ai = oai; }
        }
        mx = __shfl_sync(0xffffffffu, mx, 0);
        ai = __shfl_sync(0xffffffffu, ai, 0);
        float se = 0.f;
#pragma unroll
        for (int j = 0; j < 8; j++) se += expf(v[j] - mx);
        for (int o = 16; o; o >>= 1) se += __shfl_xor_sync(0xffffffffu, se, o);
        float lse = mx + logf(se);
        if (pass == 1) {
            int t = (int)((g_targ[n] >> (8*m)) & 0xFFull);
            float picked = lg[s*HID + t];
            if (lane == 0) { lossSum += (double)(lse - picked); hitSum += (ai == t) ? 1u : 0u; }
        } else {
            unsigned long long yb0 = g_yb[2*n], yb1 = g_yb[2*n+1];
            int cnt = g_cnt[n];
            float ps = 0.f;
#pragma unroll
            for (int q = 0; q < 4; q++) {
                int c = lane + 32*q;
                if (c < NCLS) {
                    bool act = (((c < 64) ? (yb0 >> c) : (yb1 >> (c - 64))) & 1ull) != 0;
                    if (act) ps += lg[s*HID + ctm[c]];
                }
            }
            for (int o = 16; o; o >>= 1) ps += __shfl_xor_sync(0xffffffffu, ps, o);
            if (lane == 0) lossSum += (double)(lse - ps / (float)cnt);
        }
    }
    if (lane == 0) { redL[w] = lossSum; redH[w] = hitSum; }
    __syncthreads();
    if (tid == 0) {
        double L = 0; unsigned H = 0;
        for (int i = 0; i < 8; i++) { L += redL[i]; H += redH[i]; }
        g_partLoss[pass*4096 + m*512 + blockIdx.x] = L;
        if (pass == 1) g_partHits[m*512 + blockIdx.x] = H;
    }
}

__global__ void k_final(float* out) {
    __shared__ double sL0[256], sL1[256], sD[256], sC[256];
    __shared__ unsigned long long sH[256];
    int t = threadIdx.x;
    double l0 = 0, l1 = 0, dd = 0, cc = 0; unsigned long long hh = 0;
    for (int i = t; i < 4096; i += 256) {
        l0 += g_partLoss[i];
        l1 += g_partLoss[4096 + i];
        hh += g_partHits[i];
        dd += (double)g_partDist[i];
        cc += (double)g_partCnt[i];
    }
    sL0[t] = l0; sL1[t] = l1; sD[t] = dd; sC[t] = cc; sH[t] = hh;
    __syncthreads();
    if (t < 32) {
        double L0 = 0, L1 = 0, D = 0, C = 0, H = 0;
        for (int i = t; i < 256; i += 32) {
            L0 += sL0[i]; L1 += sL1[i]; D += sD[i]; C += sC[i]; H += (double)sH[i];
        }
        for (int o = 16; o; o >>= 1) {
            L0 += __shfl_down_sync(0xffffffffu, L0, o);
            L1 += __shfl_down_sync(0xffffffffu, L1, o);
            D  += __shfl_down_sync(0xffffffffu, D, o);
            C  += __shfl_down_sync(0xffffffffu, C, o);
            H  += __shfl_down_sync(0xffffffffu, H, o);
        }
        if (t == 0) {
            double net = L0 / NROWS, map = L1 / NROWS;
            out[0] = (float)(net + map);
            out[1] = (float)net;
            out[2] = (float)map;
            out[3] = (float)(H / (double)(NROWS * MDIM));
            out[4] = (float)(D / C);
        }
    }
}

extern "C" void kernel_launch(void* const* d_in, const int* in_sizes, int n_in,
                              void* d_out, int out_size) {
    const float *x = 0, *cen = 0, *W1 = 0, *b1 = 0, *W2 = 0, *b2 = 0;
    const int *y = 0, *perm = 0, *tmap = 0, *traw = 0;
    int n64 = 0, n2048 = 0;
    for (int i = 0; i < n_in; i++) {
        int s = in_sizes[i];
        if      (s == NROWS*BITS)     x   = (const float*)d_in[i];
        else if (s == NROWS*NCLS)     y   = (const int*)d_in[i];
        else if (s == NCLS*BITS)      cen = (const float*)d_in[i];
        else if (s == MDIM*SUBD*HID)  W1  = (const float*)d_in[i];
        else if (s == MDIM*HID*HID)   W2  = (const float*)d_in[i];
        else if (s == MDIM*HID) { if (n2048++ == 0) b1 = (const float*)d_in[i]; else b2 = (const float*)d_in[i]; }
        else if (s == BITS) {
            if (n64 == 0)      perm = (const int*)d_in[i];
            else if (n64 == 1) tmap = (const int*)d_in[i];
            else               traw = (const int*)d_in[i];
            n64++;
        }
    }
    cudaFuncSetAttribute(k_gemm, cudaFuncAttributeMaxDynamicSharedMemorySize, SMEM_BYTES);
    k_init<<<1, 128>>>(cen, perm);
    k_rows<<<4096, 256>>>(x, y, perm, tmap, traw);
    k_gemm<<<dim3(NTX, MDIM, 2), 256, SMEM_BYTES>>>(W1, b1, W2, b2);
    k_final<<<1, 256>>>((float*)d_out);
}

// round 11
// speedup vs baseline: 1.4956x; 1.4016x over previous
#include <cuda_runtime.h>
#include <cuda_bf16.h>
#include <math.h>

#define NROWS 32768
#define BITS  64
#define MDIM  8
#define SUBD  8
#define HID   256
#define NCLS  100
#define TSM   128
#define NTX   (NROWS/TSM)   // 256

__device__ float              g_xp[NROWS*BITS];
__device__ unsigned long long g_flipmap[NROWS];
__device__ unsigned long long g_targ[NROWS];
__device__ unsigned long long g_yb[NROWS*2];
__device__ int                g_cnt[NROWS];
__device__ unsigned long long g_cbits[NCLS];
__device__ uint2              g_kmap, g_kraw;
__device__ __nv_bfloat16      g_w2h[MDIM*HID*HID];  // [m][o][k]
__device__ __nv_bfloat16      g_w2l[MDIM*HID*HID];
__device__ double             g_partLoss[2*2048];
__device__ unsigned           g_partHits[2048];
__device__ unsigned long long g_partDist[4096];
__device__ unsigned long long g_partCnt[4096];

// ---------------- threefry2x32 (JAX-exact) ----------------
__device__ __forceinline__ void tf2x32(unsigned k0, unsigned k1, unsigned x0, unsigned x1,
                                       unsigned &o0, unsigned &o1) {
    unsigned ks2 = k0 ^ k1 ^ 0x1BD11BDAu;
    x0 += k0; x1 += k1;
#define TFR(r) { x0 += x1; x1 = (x1<<(r))|(x1>>(32-(r))); x1 ^= x0; }
    TFR(13) TFR(15) TFR(26) TFR(6)   x0 += k1;  x1 += ks2 + 1u;
    TFR(17) TFR(29) TFR(16) TFR(24)  x0 += ks2; x1 += k0  + 2u;
    TFR(13) TFR(15) TFR(26) TFR(6)   x0 += k0;  x1 += k1  + 3u;
    TFR(17) TFR(29) TFR(16) TFR(24)  x0 += k1;  x1 += ks2 + 4u;
    TFR(13) TFR(15) TFR(26) TFR(6)   x0 += ks2; x1 += k0  + 5u;
#undef TFR
    o0 = x0; o1 = x1;
}
__device__ __forceinline__ unsigned rbits32(uint2 key, unsigned i) {
    unsigned a, b; tf2x32(key.x, key.y, 0u, i, a, b); return a ^ b;
}

__device__ unsigned long long warp_flipmask(uint2 key, int n, int lane, const int* __restrict__ tmpl) {
    unsigned r0 = rbits32(key, (unsigned)(n*BITS + lane));
    unsigned r1 = rbits32(key, (unsigned)(n*BITS + lane + 32));
    unsigned K0 = ((r0 >> 9) << 6) | (unsigned)lane;
    unsigned K1 = ((r1 >> 9) << 6) | (unsigned)(lane + 32);
    unsigned t0 = __ballot_sync(0xffffffffu, tmpl[lane]      != 0);
    unsigned t1 = __ballot_sync(0xffffffffu, tmpl[lane + 32] != 0);
    unsigned long long flip = 0ull;
    unsigned mm = t0;
    while (mm) {
        int t = __ffs(mm) - 1; mm &= mm - 1;
        unsigned Kt = __shfl_sync(0xffffffffu, K0, t);
        int rank = __popc(__ballot_sync(0xffffffffu, K0 < Kt))
                 + __popc(__ballot_sync(0xffffffffu, K1 < Kt));
        flip |= 1ull << rank;
    }
    mm = t1;
    while (mm) {
        int t = __ffs(mm) - 1; mm &= mm - 1;
        unsigned Kt = __shfl_sync(0xffffffffu, K1, t);
        int rank = __popc(__ballot_sync(0xffffffffu, K0 < Kt))
                 + __popc(__ballot_sync(0xffffffffu, K1 < Kt));
        flip |= 1ull << rank;
    }
    return flip;
}

__global__ void k_init(const float* __restrict__ cen, const int* __restrict__ perm) {
    int t = threadIdx.x;
    if (t == 0) {
        unsigned a, b;
        tf2x32(0u, 1u, 0u, 0u, a, b); g_kmap = make_uint2(a, b);
        tf2x32(0u, 1u, 0u, 1u, a, b); g_kraw = make_uint2(a, b);
    }
    if (t < NCLS) {
        unsigned long long bits = 0ull;
        for (int k = 0; k < BITS; k++)
            if (cen[t*BITS + perm[k]] > 0.f) bits |= 1ull << k;
        g_cbits[t] = bits;
    }
}

__global__ void k_prep(const float* __restrict__ W2) {
    int idx = blockIdx.x * 256 + threadIdx.x;
    int m = idx >> 16, o = (idx >> 8) & 255, k = idx & 255;
    float v = W2[(m*HID + k)*HID + o];
    __nv_bfloat16 hi = __float2bfloat16(v);
    __nv_bfloat16 lo = __float2bfloat16(v - __bfloat162float(hi));
    g_w2h[idx] = hi; g_w2l[idx] = lo;
}

__global__ void k_rows(const float* __restrict__ x, const int* __restrict__ y,
                       const int* __restrict__ perm,
                       const int* __restrict__ tmap, const int* __restrict__ traw) {
    __shared__ int perm_s[BITS];
    __shared__ unsigned long long cb_s[NCLS];
    __shared__ unsigned wdist[8], wcnt[8];
    const int tid = threadIdx.x, lane = tid & 31, w = tid >> 5;
    if (tid < BITS) perm_s[tid] = perm[tid];
    if (tid < NCLS) cb_s[tid] = g_cbits[tid];
    __syncthreads();

    const int n = blockIdx.x * 8 + w;
    const int c0 = lane, c1 = lane + 32;
    float v0 = x[n*BITS + perm_s[c0]];
    float v1 = x[n*BITS + perm_s[c1]];
    g_xp[n*BITS + c0] = v0;
    g_xp[n*BITS + c1] = v1;

    g_flipmap[n] = warp_flipmask(g_kmap, n, lane, tmap);
    unsigned long long frawm = warp_flipmask(g_kraw, n, lane, traw);

    bool bit0 = ((frawm >> c0) & 1ull) ? (v0 < 0.f) : (v0 > 0.f);
    bool bit1 = ((frawm >> c1) & 1ull) ? (v1 < 0.f) : (v1 > 0.f);
    unsigned lo = __ballot_sync(0xffffffffu, bit0);
    unsigned hi = __ballot_sync(0xffffffffu, bit1);
    g_targ[n] = (unsigned long long)lo | ((unsigned long long)hi << 32);

    lo = __ballot_sync(0xffffffffu, v0 > 0.f);
    hi = __ballot_sync(0xffffffffu, v1 > 0.f);
    unsigned long long cx = (unsigned long long)lo | ((unsigned long long)hi << 32);

    const int* yr = y + n*NCLS;
    unsigned bal[4]; unsigned mydist = 0;
#pragma unroll
    for (int q = 0; q < 4; q++) {
        int c = lane + 32*q;
        bool a = (c < NCLS) ? (yr[c] > 0) : false;
        bal[q] = __ballot_sync(0xffffffffu, a);
        if (a) mydist += (unsigned)__popcll(cx ^ cb_s[c]);
    }
    unsigned long long yb0 = (unsigned long long)bal[0] | ((unsigned long long)bal[1] << 32);
    unsigned long long yb1 = (unsigned long long)bal[2] | ((unsigned long long)bal[3] << 32);
    int cnt = __popcll(yb0) + __popcll(yb1);
    if (lane == 0) { g_yb[2*n] = yb0; g_yb[2*n+1] = yb1; g_cnt[n] = cnt; }

    for (int o = 16; o; o >>= 1) mydist += __shfl_down_sync(0xffffffffu, mydist, o);
    if (lane == 0) { wdist[w] = mydist; wcnt[w] = (unsigned)cnt; }
    __syncthreads();
    if (tid == 0) {
        unsigned D = 0, C = 0;
        for (int i = 0; i < 8; i++) { D += wdist[i]; C += wcnt[i]; }
        g_partDist[blockIdx.x] = D;
        g_partCnt[blockIdx.x] = C;
    }
}

// ---------------- mma.sync helpers (base PTX, no 'a' features) ----------------
__device__ __forceinline__ unsigned smem_u32(const void* p) {
    unsigned a;
    asm("{ .reg .u64 t; cvta.to.shared.u64 t, %1; cvt.u32.u64 %0, t; }" : "=r"(a) : "l"(p));
    return a;
}
__device__ __forceinline__ void ldsm4(unsigned* r, unsigned addr) {
    asm volatile("ldmatrix.sync.aligned.m8n8.x4.shared.b16 {%0,%1,%2,%3}, [%4];"
        : "=r"(r[0]), "=r"(r[1]), "=r"(r[2]), "=r"(r[3]) : "r"(addr));
}
__device__ __forceinline__ void mma16816(float* d, const unsigned* a, const unsigned* b) {
    asm volatile("mma.sync.aligned.m16n8k16.row.col.f32.bf16.bf16.f32 "
        "{%0,%1,%2,%3}, {%4,%5,%6,%7}, {%8,%9}, {%0,%1,%2,%3};"
        : "+f"(d[0]), "+f"(d[1]), "+f"(d[2]), "+f"(d[3])
        : "r"(a[0]), "r"(a[1]), "r"(a[2]), "r"(a[3]), "r"(b[0]), "r"(b[1]));
}

// SMEM layout (bytes)
#define APITCH 528          // 264 bf16 per row (conflict-free ldmatrix)
#define SM_AH 0             // 128*528 = 67584
#define SM_AL 67584         // 67584  -> 135168
#define SM_B  135168        // 2 splits * 256 rows * 48B = 24576 -> 159744
#define BPITCH 48
#define BSPL  12288
#define SM_B2 159744        // 1024
#define SM_XS 160768        // 4096
#define SM_CT 164864        // 400 (+pad)
#define SM_RL 165264        // 16*8
#define SM_RH 165392        // 64
#define SMEM_BYTES 165504
#define LGP 257

__global__ void __launch_bounds__(512, 1)
k_mma(const float* __restrict__ W1, const float* __restrict__ b1,
      const float* __restrict__ b2) {
    extern __shared__ char smem[];
    const unsigned sb = smem_u32(smem);
    const int tid = threadIdx.x, lane = tid & 31, w = tid >> 5;
    const int m = blockIdx.y, pass = blockIdx.z;
    const int s0 = blockIdx.x * TSM;
    const int mt = w & 7, nh = w >> 3;      // warp tile: rows mt*16..+16, cols nh*128..+128
    float* b2s = (float*)(smem + SM_B2);
    float* xs  = (float*)(smem + SM_XS);
    int* ctm = (int*)(smem + SM_CT);
    double* redL = (double*)(smem + SM_RL);
    unsigned* redH = (unsigned*)(smem + SM_RH);
    float* lg = (float*)smem;

    if (tid < HID) b2s[tid] = b2[m*HID + tid];
    if (pass == 0 && tid < NCLS) ctm[tid] = (int)((g_cbits[tid] >> (8*m)) & 0xFFull);
    for (int i = tid; i < TSM*SUBD; i += 512) {
        int s = i >> 3, k = i & 7;
        float v = g_xp[(s0 + s)*BITS + m*SUBD + k];
        if (pass == 1 && ((g_flipmap[s0 + s] >> (m*SUBD + k)) & 1ull)) v = -v;
        xs[i] = v;
    }
    __syncthreads();

    // layer 1: thread -> hidden unit (tid&255), sample half (tid>>8); bf16 hi/lo to A
    {
        const int u = tid & 255, half = tid >> 8;
        float w1r[SUBD];
#pragma unroll
        for (int k = 0; k < SUBD; k++) w1r[k] = W1[(m*SUBD + k)*HID + u];
        const float b1v = b1[m*HID + u];
        for (int s = half*64; s < half*64 + 64; s++) {
            float pre = b1v;
#pragma unroll
            for (int k = 0; k < SUBD; k++) pre += xs[s*SUBD + k] * w1r[k];
            float hv = pre / (1.f + expf(-pre));
            __nv_bfloat16 hi = __float2bfloat16(hv);
            __nv_bfloat16 lo = __float2bfloat16(hv - __bfloat162float(hi));
            *(__nv_bfloat16*)(smem + SM_AH + s*APITCH + u*2) = hi;
            *(__nv_bfloat16*)(smem + SM_AL + s*APITCH + u*2) = lo;
        }
    }

    float acc[16][4];
#pragma unroll
    for (int i = 0; i < 16; i++)
#pragma unroll
        for (int j = 0; j < 4; j++) acc[i][j] = 0.f;

    // ldmatrix lane addressing
    const unsigned aOff = (unsigned)((mt*16 + (lane & 15))*APITCH + (lane >> 4)*16);
    const unsigned bRow = (unsigned)(nh*128 + (lane & 7) + ((lane >> 4) << 3));
    const unsigned bCol = (unsigned)(((lane >> 3) & 1) * 16);

    for (int c = 0; c < 16; c++) {
        const int k0 = c*16;
        __syncthreads();                       // prior chunk's B fully consumed
        {   // stage B chunk: [256 o][16 k] hi+lo
            const int split = tid >> 8, o = tid & 255;
            const __nv_bfloat16* src = (split ? g_w2l : g_w2h) + ((m*HID + o)*HID + k0);
            uint4 v0 = *(const uint4*)src;
            uint4 v1 = *(const uint4*)(src + 8);
            char* dst = smem + SM_B + split*BSPL + o*BPITCH;
            *(uint4*)dst = v0; *(uint4*)(dst + 16) = v1;
        }
        __syncthreads();
        unsigned ah[4], al[4];
        ldsm4(ah, sb + SM_AH + aOff + (unsigned)(k0*2));
        ldsm4(al, sb + SM_AL + aOff + (unsigned)(k0*2));
#pragma unroll
        for (int nt = 0; nt < 8; nt++) {
            unsigned bh[4], bl[4];
            unsigned ba = sb + SM_B + (bRow + nt*16)*BPITCH + bCol;
            ldsm4(bh, ba);
            ldsm4(bl, ba + BSPL);
            mma16816(acc[2*nt],   ah, bh);
            mma16816(acc[2*nt],   al, bh);
            mma16816(acc[2*nt],   ah, bl);
            mma16816(acc[2*nt+1], ah, bh + 2);
            mma16816(acc[2*nt+1], al, bh + 2);
            mma16816(acc[2*nt+1], ah, bl + 2);
        }
    }
    __syncthreads();

    // write logits (+b2) to smem, pitch 257 (overlays A region)
    {
        const int gid = lane >> 2, q = lane & 3;
        const int r0 = mt*16 + gid;
#pragma unroll
        for (int nt = 0; nt < 16; nt++) {
            int c0 = nh*128 + nt*8 + q*2;
            lg[r0*LGP + c0]       = acc[nt][0] + b2s[c0];
            lg[r0*LGP + c0 + 1]   = acc[nt][1] + b2s[c0 + 1];
            lg[(r0+8)*LGP + c0]   = acc[nt][2] + b2s[c0];
            lg[(r0+8)*LGP + c0+1] = acc[nt][3] + b2s[c0 + 1];
        }
    }
    __syncthreads();

    // epilogue: warp w -> samples w*8..w*8+7
    double lossSum = 0.0; unsigned hitSum = 0;
    for (int si = 0; si < 8; si++) {
        int s = w*8 + si, n = s0 + s;
        const float* row = lg + s*LGP;
        float v[8];
#pragma unroll
        for (int j = 0; j < 8; j++) v[j] = row[lane + 32*j];
        float mx = v[0]; int ai = lane;
#pragma unroll
        for (int j = 1; j < 8; j++) if (v[j] > mx) { mx = v[j]; ai = lane + 32*j; }
        for (int o = 16; o; o >>= 1) {
            float omx = __shfl_down_sync(0xffffffffu, mx, o);
            int   oai = __shfl_down_sync(0xffffffffu, ai, o);
            if (omx > mx || (omx == mx && oai < ai)) { mx = omx; ai = oai; }
        }
        mx = __shfl_sync(0xffffffffu, mx, 0);
        ai = __shfl_sync(0xffffffffu, ai, 0);
        float se = 0.f;
#pragma unroll
        for (int j = 0; j < 8; j++) se += expf(v[j] - mx);
        for (int o = 16; o; o >>= 1) se += __shfl_xor_sync(0xffffffffu, se, o);
        float lse = mx + logf(se);
        if (pass == 1) {
            int t = (int)((g_targ[n] >> (8*m)) & 0xFFull);
            float picked = row[t];
            if (lane == 0) { lossSum += (double)(lse - picked); hitSum += (ai == t) ? 1u : 0u; }
        } else {
            unsigned long long yb0 = g_yb[2*n], yb1 = g_yb[2*n+1];
            int cnt = g_cnt[n];
            float ps = 0.f;
#pragma unroll
            for (int q = 0; q < 4; q++) {
                int cc = lane + 32*q;
                if (cc < NCLS) {
                    bool act = (((cc < 64) ? (yb0 >> cc) : (yb1 >> (cc - 64))) & 1ull) != 0;
                    if (act) ps += row[ctm[cc]];
                }
            }
            for (int o = 16; o; o >>= 1) ps += __shfl_xor_sync(0xffffffffu, ps, o);
            if (lane == 0) lossSum += (double)(lse - ps / (float)cnt);
        }
    }
    if (lane == 0) { redL[w] = lossSum; redH[w] = hitSum; }
    __syncthreads();
    if (tid == 0) {
        double L = 0; unsigned H = 0;
        for (int i = 0; i < 16; i++) { L += redL[i]; H += redH[i]; }
        g_partLoss[pass*2048 + m*NTX + blockIdx.x] = L;
        if (pass == 1) g_partHits[m*NTX + blockIdx.x] = H;
    }
}

__global__ void k_final(float* out) {
    __shared__ double sL0[256], sL1[256], sD[256], sC[256];
    __shared__ unsigned long long sH[256];
    int t = threadIdx.x;
    double l0 = 0, l1 = 0, dd = 0, cc = 0; unsigned long long hh = 0;
    for (int i = t; i < 2048; i += 256) {
        l0 += g_partLoss[i];
        l1 += g_partLoss[2048 + i];
        hh += g_partHits[i];
    }
    for (int i = t; i < 4096; i += 256) {
        dd += (double)g_partDist[i];
        cc += (double)g_partCnt[i];
    }
    sL0[t] = l0; sL1[t] = l1; sD[t] = dd; sC[t] = cc; sH[t] = hh;
    __syncthreads();
    if (t < 32) {
        double L0 = 0, L1 = 0, D = 0, C = 0, H = 0;
        for (int i = t; i < 256; i += 32) {
            L0 += sL0[i]; L1 += sL1[i]; D += sD[i]; C += sC[i]; H += (double)sH[i];
        }
        for (int o = 16; o; o >>= 1) {
            L0 += __shfl_down_sync(0xffffffffu, L0, o);
            L1 += __shfl_down_sync(0xffffffffu, L1, o);
            D  += __shfl_down_sync(0xffffffffu, D, o);
            C  += __shfl_down_sync(0xffffffffu, C, o);
            H  += __shfl_down_sync(0xffffffffu, H, o);
        }
        if (t == 0) {
            double net = L0 / NROWS, map = L1 / NROWS;
            out[0] = (float)(net + map);
            out[1] = (float)net;
            out[2] = (float)map;
            out[3] = (float)(H / (double)(NROWS * MDIM));
            out[4] = (float)(D / C);
        }
    }
}

extern "C" void kernel_launch(void* const* d_in, const int* in_sizes, int n_in,
                              void* d_out, int out_size) {
    const float *x = 0, *cen = 0, *W1 = 0, *b1 = 0, *W2 = 0, *b2 = 0;
    const int *y = 0, *perm = 0, *tmap = 0, *traw = 0;
    int n64 = 0, n2048 = 0;
    for (int i = 0; i < n_in; i++) {
        int s = in_sizes[i];
        if      (s == NROWS*BITS)     x   = (const float*)d_in[i];
        else if (s == NROWS*NCLS)     y   = (const int*)d_in[i];
        else if (s == NCLS*BITS)      cen = (const float*)d_in[i];
        else if (s == MDIM*SUBD*HID)  W1  = (const float*)d_in[i];
        else if (s == MDIM*HID*HID)   W2  = (const float*)d_in[i];
        else if (s == MDIM*HID) { if (n2048++ == 0) b1 = (const float*)d_in[i]; else b2 = (const float*)d_in[i]; }
        else if (s == BITS) {
            if (n64 == 0)      perm = (const int*)d_in[i];
            else if (n64 == 1) tmap = (const int*)d_in[i];
            else               traw = (const int*)d_in[i];
            n64++;
        }
    }
    cudaFuncSetAttribute(k_mma, cudaFuncAttributeMaxDynamicSharedMemorySize, SMEM_BYTES);
    k_init<<<1, 128>>>(cen, perm);
    k_prep<<<2048, 256>>>(W2);
    k_rows<<<4096, 256>>>(x, y, perm, tmap, traw);
    k_mma<<<dim3(NTX, MDIM, 2), 512, SMEM_BYTES>>>(W1, b1, b2);
    k_final<<<1, 256>>>((float*)d_out);
}

// round 12
// speedup vs baseline: 1.7771x; 1.1882x over previous
#include <cuda_runtime.h>
#include <cuda_bf16.h>
#include <math.h>

#define NROWS 32768
#define BITS  64
#define MDIM  8
#define SUBD  8
#define HID   256
#define NCLS  100
#define TSM   128
#define NTX   (NROWS/TSM)   // 256

__device__ float              g_xp[NROWS*BITS];
__device__ unsigned long long g_flipmap[NROWS];
__device__ unsigned long long g_targ[NROWS];
__device__ unsigned long long g_yb[NROWS*2];
__device__ int                g_cnt[NROWS];
__device__ unsigned long long g_cbits[NCLS];
__device__ uint2              g_kmap, g_kraw;
__device__ __nv_bfloat16      g_w2h[MDIM*HID*HID];  // [m][o][k]
__device__ __nv_bfloat16      g_w2l[MDIM*HID*HID];
__device__ double             g_partLoss[2*2048];
__device__ unsigned           g_partHits[2048];
__device__ unsigned long long g_partDist[4096];
__device__ unsigned long long g_partCnt[4096];

// ---------------- threefry2x32 (JAX-exact) ----------------
__device__ __forceinline__ void tf2x32(unsigned k0, unsigned k1, unsigned x0, unsigned x1,
                                       unsigned &o0, unsigned &o1) {
    unsigned ks2 = k0 ^ k1 ^ 0x1BD11BDAu;
    x0 += k0; x1 += k1;
#define TFR(r) { x0 += x1; x1 = (x1<<(r))|(x1>>(32-(r))); x1 ^= x0; }
    TFR(13) TFR(15) TFR(26) TFR(6)   x0 += k1;  x1 += ks2 + 1u;
    TFR(17) TFR(29) TFR(16) TFR(24)  x0 += ks2; x1 += k0  + 2u;
    TFR(13) TFR(15) TFR(26) TFR(6)   x0 += k0;  x1 += k1  + 3u;
    TFR(17) TFR(29) TFR(16) TFR(24)  x0 += k1;  x1 += ks2 + 4u;
    TFR(13) TFR(15) TFR(26) TFR(6)   x0 += ks2; x1 += k0  + 5u;
#undef TFR
    o0 = x0; o1 = x1;
}
__device__ __forceinline__ unsigned rbits32(uint2 key, unsigned i) {
    unsigned a, b; tf2x32(key.x, key.y, 0u, i, a, b); return a ^ b;
}

__device__ unsigned long long warp_flipmask(uint2 key, int n, int lane, const int* __restrict__ tmpl) {
    unsigned r0 = rbits32(key, (unsigned)(n*BITS + lane));
    unsigned r1 = rbits32(key, (unsigned)(n*BITS + lane + 32));
    unsigned K0 = ((r0 >> 9) << 6) | (unsigned)lane;
    unsigned K1 = ((r1 >> 9) << 6) | (unsigned)(lane + 32);
    unsigned t0 = __ballot_sync(0xffffffffu, tmpl[lane]      != 0);
    unsigned t1 = __ballot_sync(0xffffffffu, tmpl[lane + 32] != 0);
    unsigned long long flip = 0ull;
    unsigned mm = t0;
    while (mm) {
        int t = __ffs(mm) - 1; mm &= mm - 1;
        unsigned Kt = __shfl_sync(0xffffffffu, K0, t);
        int rank = __popc(__ballot_sync(0xffffffffu, K0 < Kt))
                 + __popc(__ballot_sync(0xffffffffu, K1 < Kt));
        flip |= 1ull << rank;
    }
    mm = t1;
    while (mm) {
        int t = __ffs(mm) - 1; mm &= mm - 1;
        unsigned Kt = __shfl_sync(0xffffffffu, K1, t);
        int rank = __popc(__ballot_sync(0xffffffffu, K0 < Kt))
                 + __popc(__ballot_sync(0xffffffffu, K1 < Kt));
        flip |= 1ull << rank;
    }
    return flip;
}

__global__ void k_init(const float* __restrict__ cen, const int* __restrict__ perm) {
    int t = threadIdx.x;
    if (t == 0) {
        unsigned a, b;
        tf2x32(0u, 1u, 0u, 0u, a, b); g_kmap = make_uint2(a, b);
        tf2x32(0u, 1u, 0u, 1u, a, b); g_kraw = make_uint2(a, b);
    }
    if (t < NCLS) {
        unsigned long long bits = 0ull;
        for (int k = 0; k < BITS; k++)
            if (cen[t*BITS + perm[k]] > 0.f) bits |= 1ull << k;
        g_cbits[t] = bits;
    }
}

__global__ void k_prep(const float* __restrict__ W2) {
    int idx = blockIdx.x * 256 + threadIdx.x;
    int m = idx >> 16, o = (idx >> 8) & 255, k = idx & 255;
    float v = W2[(m*HID + k)*HID + o];
    __nv_bfloat16 hi = __float2bfloat16(v);
    __nv_bfloat16 lo = __float2bfloat16(v - __bfloat162float(hi));
    g_w2h[idx] = hi; g_w2l[idx] = lo;
}

__global__ void k_rows(const float* __restrict__ x, const int* __restrict__ y,
                       const int* __restrict__ perm,
                       const int* __restrict__ tmap, const int* __restrict__ traw) {
    __shared__ int perm_s[BITS];
    __shared__ unsigned long long cb_s[NCLS];
    __shared__ unsigned wdist[8], wcnt[8];
    const int tid = threadIdx.x, lane = tid & 31, w = tid >> 5;
    if (tid < BITS) perm_s[tid] = perm[tid];
    if (tid < NCLS) cb_s[tid] = g_cbits[tid];
    __syncthreads();

    const int n = blockIdx.x * 8 + w;
    const int c0 = lane, c1 = lane + 32;
    float v0 = x[n*BITS + perm_s[c0]];
    float v1 = x[n*BITS + perm_s[c1]];
    g_xp[n*BITS + c0] = v0;
    g_xp[n*BITS + c1] = v1;

    g_flipmap[n] = warp_flipmask(g_kmap, n, lane, tmap);
    unsigned long long frawm = warp_flipmask(g_kraw, n, lane, traw);

    bool bit0 = ((frawm >> c0) & 1ull) ? (v0 < 0.f) : (v0 > 0.f);
    bool bit1 = ((frawm >> c1) & 1ull) ? (v1 < 0.f) : (v1 > 0.f);
    unsigned lo = __ballot_sync(0xffffffffu, bit0);
    unsigned hi = __ballot_sync(0xffffffffu, bit1);
    g_targ[n] = (unsigned long long)lo | ((unsigned long long)hi << 32);

    lo = __ballot_sync(0xffffffffu, v0 > 0.f);
    hi = __ballot_sync(0xffffffffu, v1 > 0.f);
    unsigned long long cx = (unsigned long long)lo | ((unsigned long long)hi << 32);

    const int* yr = y + n*NCLS;
    unsigned bal[4]; unsigned mydist = 0;
#pragma unroll
    for (int q = 0; q < 4; q++) {
        int c = lane + 32*q;
        bool a = (c < NCLS) ? (yr[c] > 0) : false;
        bal[q] = __ballot_sync(0xffffffffu, a);
        if (a) mydist += (unsigned)__popcll(cx ^ cb_s[c]);
    }
    unsigned long long yb0 = (unsigned long long)bal[0] | ((unsigned long long)bal[1] << 32);
    unsigned long long yb1 = (unsigned long long)bal[2] | ((unsigned long long)bal[3] << 32);
    int cnt = __popcll(yb0) + __popcll(yb1);
    if (lane == 0) { g_yb[2*n] = yb0; g_yb[2*n+1] = yb1; g_cnt[n] = cnt; }

    for (int o = 16; o; o >>= 1) mydist += __shfl_down_sync(0xffffffffu, mydist, o);
    if (lane == 0) { wdist[w] = mydist; wcnt[w] = (unsigned)cnt; }
    __syncthreads();
    if (tid == 0) {
        unsigned D = 0, C = 0;
        for (int i = 0; i < 8; i++) { D += wdist[i]; C += wcnt[i]; }
        g_partDist[blockIdx.x] = D;
        g_partCnt[blockIdx.x] = C;
    }
}

// ---------------- mma.sync helpers ----------------
__device__ __forceinline__ unsigned smem_u32(const void* p) {
    unsigned a;
    asm("{ .reg .u64 t; cvta.to.shared.u64 t, %1; cvt.u32.u64 %0, t; }" : "=r"(a) : "l"(p));
    return a;
}
__device__ __forceinline__ void ldsm4(unsigned* r, unsigned addr) {
    asm volatile("ldmatrix.sync.aligned.m8n8.x4.shared.b16 {%0,%1,%2,%3}, [%4];"
        : "=r"(r[0]), "=r"(r[1]), "=r"(r[2]), "=r"(r[3]) : "r"(addr));
}
__device__ __forceinline__ void mma16816(float* d, const unsigned* a, const unsigned* b) {
    asm volatile("mma.sync.aligned.m16n8k16.row.col.f32.bf16.bf16.f32 "
        "{%0,%1,%2,%3}, {%4,%5,%6,%7}, {%8,%9}, {%0,%1,%2,%3};"
        : "+f"(d[0]), "+f"(d[1]), "+f"(d[2]), "+f"(d[3])
        : "r"(a[0]), "r"(a[1]), "r"(a[2]), "r"(a[3]), "r"(b[0]), "r"(b[1]));
}

// SMEM layout (bytes)
#define APITCH 528
#define SM_AH 0              // 128*528 = 67584
#define SM_AL 67584          // -> 135168
#define BPITCH 48
#define BSPL  12288          // one split = 256*48
#define SM_B0 135168         // 24576
#define SM_B1 159744         // 24576 -> 184320
#define SM_B2 184320         // 1024
#define SM_XS 185344         // 4096
#define SM_CT 189440         // 448
#define SM_RL 189888         // 128
#define SM_RH 190016         // 64
#define SMEM_BYTES 190080
#define LGP 257

__global__ void __launch_bounds__(512, 1)
k_mma(const float* __restrict__ W1, const float* __restrict__ b1,
      const float* __restrict__ b2) {
    extern __shared__ char smem[];
    const unsigned sb = smem_u32(smem);
    const int tid = threadIdx.x, lane = tid & 31, w = tid >> 5;
    const int m = blockIdx.y, pass = blockIdx.z;
    const int s0 = blockIdx.x * TSM;
    const int mt = w & 3, nt = w >> 2;      // warp tile: M32 (rows mt*32) x N64 (cols nt*64)
    float* b2s = (float*)(smem + SM_B2);
    float* xs  = (float*)(smem + SM_XS);
    int* ctm = (int*)(smem + SM_CT);
    double* redL = (double*)(smem + SM_RL);
    unsigned* redH = (unsigned*)(smem + SM_RH);
    float* lg = (float*)smem;

    if (tid < HID) b2s[tid] = b2[m*HID + tid];
    if (pass == 0 && tid < NCLS) ctm[tid] = (int)((g_cbits[tid] >> (8*m)) & 0xFFull);
    for (int i = tid; i < TSM*SUBD; i += 512) {
        int s = i >> 3, k = i & 7;
        float v = g_xp[(s0 + s)*BITS + m*SUBD + k];
        if (pass == 1 && ((g_flipmap[s0 + s] >> (m*SUBD + k)) & 1ull)) v = -v;
        xs[i] = v;
    }
    __syncthreads();

    // layer 1: thread -> hidden unit (tid&255), sample half (tid>>8); bf16 hi/lo to A
    {
        const int u = tid & 255, half = tid >> 8;
        float w1r[SUBD];
#pragma unroll
        for (int k = 0; k < SUBD; k++) w1r[k] = W1[(m*SUBD + k)*HID + u];
        const float b1v = b1[m*HID + u];
        for (int s = half*64; s < half*64 + 64; s++) {
            float pre = b1v;
#pragma unroll
            for (int k = 0; k < SUBD; k++) pre += xs[s*SUBD + k] * w1r[k];
            float hv = pre / (1.f + expf(-pre));
            __nv_bfloat16 hi = __float2bfloat16(hv);
            __nv_bfloat16 lo = __float2bfloat16(hv - __bfloat162float(hi));
            *(__nv_bfloat16*)(smem + SM_AH + s*APITCH + u*2) = hi;
            *(__nv_bfloat16*)(smem + SM_AL + s*APITCH + u*2) = lo;
        }
    }

    // B staging setup (thread -> (split, o) row; 32 B per chunk)
    const int sSplit = tid >> 8, sO = tid & 255;
    const __nv_bfloat16* sBase = (sSplit ? g_w2l : g_w2h) + (m*HID + sO)*HID;
    char* sDst0 = smem + SM_B0 + sSplit*BSPL + sO*BPITCH;
    char* sDst1 = smem + SM_B1 + sSplit*BSPL + sO*BPITCH;
    {
        uint4 v0 = *(const uint4*)(sBase);
        uint4 v1 = *(const uint4*)(sBase + 8);
        *(uint4*)sDst0 = v0; *(uint4*)(sDst0 + 16) = v1;
    }
    __syncthreads();   // A writes + chunk0 staging visible

    float acc[2][8][4];
#pragma unroll
    for (int t = 0; t < 2; t++)
#pragma unroll
        for (int g = 0; g < 8; g++)
#pragma unroll
            for (int j = 0; j < 4; j++) acc[t][g][j] = 0.f;

    const unsigned aOff = sb + SM_AH + (unsigned)((mt*32 + (lane & 15))*APITCH + (lane >> 4)*16);
    const unsigned bOff = (unsigned)((nt*64 + (lane & 7) + ((lane >> 4) << 3))*BPITCH + ((lane >> 3) & 1)*16);

    for (int c = 0; c < 16; c++) {
        uint4 v0, v1;
        if (c < 15) {
            v0 = *(const uint4*)(sBase + (c+1)*16);
            v1 = *(const uint4*)(sBase + (c+1)*16 + 8);
        }
        const unsigned bufB = sb + ((c & 1) ? SM_B1 : SM_B0);
        unsigned ah0[4], ah1[4], al0[4], al1[4];
        ldsm4(ah0, aOff + (unsigned)(c*32));
        ldsm4(ah1, aOff + (unsigned)(16*APITCH + c*32));
        ldsm4(al0, aOff + (unsigned)(67584 + c*32));
        ldsm4(al1, aOff + (unsigned)(67584 + 16*APITCH + c*32));
#pragma unroll
        for (int g2 = 0; g2 < 4; g2++) {
            unsigned bh[4], bl[4];
            unsigned ba = bufB + bOff + (unsigned)(g2*16*BPITCH);
            ldsm4(bh, ba);
            ldsm4(bl, ba + BSPL);
            mma16816(acc[0][2*g2],   ah0, bh);
            mma16816(acc[0][2*g2],   al0, bh);
            mma16816(acc[0][2*g2],   ah0, bl);
            mma16816(acc[0][2*g2+1], ah0, bh + 2);
            mma16816(acc[0][2*g2+1], al0, bh + 2);
            mma16816(acc[0][2*g2+1], ah0, bl + 2);
            mma16816(acc[1][2*g2],   ah1, bh);
            mma16816(acc[1][2*g2],   al1, bh);
            mma16816(acc[1][2*g2],   ah1, bl);
            mma16816(acc[1][2*g2+1], ah1, bh + 2);
            mma16816(acc[1][2*g2+1], al1, bh + 2);
            mma16816(acc[1][2*g2+1], ah1, bl + 2);
        }
        if (c < 15) {
            char* d = (c & 1) ? sDst0 : sDst1;   // buffer (c+1)&1
            *(uint4*)d = v0; *(uint4*)(d + 16) = v1;
        }
        __syncthreads();
    }

    // write logits (+b2) to smem, pitch LGP (overlays A region)
    {
        const int gid = lane >> 2, q = lane & 3;
#pragma unroll
        for (int t = 0; t < 2; t++) {
            int r0 = mt*32 + t*16 + gid;
#pragma unroll
            for (int g = 0; g < 8; g++) {
                int c0 = nt*64 + g*8 + q*2;
                lg[r0*LGP + c0]       = acc[t][g][0] + b2s[c0];
                lg[r0*LGP + c0 + 1]   = acc[t][g][1] + b2s[c0 + 1];
                lg[(r0+8)*LGP + c0]   = acc[t][g][2] + b2s[c0];
                lg[(r0+8)*LGP + c0+1] = acc[t][g][3] + b2s[c0 + 1];
            }
        }
    }
    __syncthreads();

    // epilogue: warp w -> samples w*8..w*8+7
    double lossSum = 0.0; unsigned hitSum = 0;
    for (int si = 0; si < 8; si++) {
        int s = w*8 + si, n = s0 + s;
        const float* row = lg + s*LGP;
        float v[8];
#pragma unroll
        for (int j = 0; j < 8; j++) v[j] = row[lane + 32*j];
        float mx = v[0]; int ai = lane;
#pragma unroll
        for (int j = 1; j < 8; j++) if (v[j] > mx) { mx = v[j]; ai = lane + 32*j; }
        for (int o = 16; o; o >>= 1) {
            float omx = __shfl_down_sync(0xffffffffu, mx, o);
            int   oai = __shfl_down_sync(0xffffffffu, ai, o);
            if (omx > mx || (omx == mx && oai < ai)) { mx = omx; ai = oai; }
        }
        mx = __shfl_sync(0xffffffffu, mx, 0);
        ai = __shfl_sync(0xffffffffu, ai, 0);
        float se = 0.f;
#pragma unroll
        for (int j = 0; j < 8; j++) se += expf(v[j] - mx);
        for (int o = 16; o; o >>= 1) se += __shfl_xor_sync(0xffffffffu, se, o);
        float lse = mx + logf(se);
        if (pass == 1) {
            int t = (int)((g_targ[n] >> (8*m)) & 0xFFull);
            float picked = row[t];
            if (lane == 0) { lossSum += (double)(lse - picked); hitSum += (ai == t) ? 1u : 0u; }
        } else {
            unsigned long long yb0 = g_yb[2*n], yb1 = g_yb[2*n+1];
            int cnt = g_cnt[n];
            float ps = 0.f;
#pragma unroll
            for (int q = 0; q < 4; q++) {
                int cc = lane + 32*q;
                if (cc < NCLS) {
                    bool act = (((cc < 64) ? (yb0 >> cc) : (yb1 >> (cc - 64))) & 1ull) != 0;
                    if (act) ps += row[ctm[cc]];
                }
            }
            for (int o = 16; o; o >>= 1) ps += __shfl_xor_sync(0xffffffffu, ps, o);
            if (lane == 0) lossSum += (double)(lse - ps / (float)cnt);
        }
    }
    if (lane == 0) { redL[w] = lossSum; redH[w] = hitSum; }
    __syncthreads();
    if (tid == 0) {
        double L = 0; unsigned H = 0;
        for (int i = 0; i < 16; i++) { L += redL[i]; H += redH[i]; }
        g_partLoss[pass*2048 + m*NTX + blockIdx.x] = L;
        if (pass == 1) g_partHits[m*NTX + blockIdx.x] = H;
    }
}

__global__ void k_final(float* out) {
    __shared__ double sL0[256], sL1[256], sD[256], sC[256];
    __shared__ unsigned long long sH[256];
    int t = threadIdx.x;
    double l0 = 0, l1 = 0, dd = 0, cc = 0; unsigned long long hh = 0;
    for (int i = t; i < 2048; i += 256) {
        l0 += g_partLoss[i];
        l1 += g_partLoss[2048 + i];
        hh += g_partHits[i];
    }
    for (int i = t; i < 4096; i += 256) {
        dd += (double)g_partDist[i];
        cc += (double)g_partCnt[i];
    }
    sL0[t] = l0; sL1[t] = l1; sD[t] = dd; sC[t] = cc; sH[t] = hh;
    __syncthreads();
    if (t < 32) {
        double L0 = 0, L1 = 0, D = 0, C = 0, H = 0;
        for (int i = t; i < 256; i += 32) {
            L0 += sL0[i]; L1 += sL1[i]; D += sD[i]; C += sC[i]; H += (double)sH[i];
        }
        for (int o = 16; o; o >>= 1) {
            L0 += __shfl_down_sync(0xffffffffu, L0, o);
            L1 += __shfl_down_sync(0xffffffffu, L1, o);
            D  += __shfl_down_sync(0xffffffffu, D, o);
            C  += __shfl_down_sync(0xffffffffu, C, o);
            H  += __shfl_down_sync(0xffffffffu, H, o);
        }
        if (t == 0) {
            double net = L0 / NROWS, map = L1 / NROWS;
            out[0] = (float)(net + map);
            out[1] = (float)net;
            out[2] = (float)map;
            out[3] = (float)(H / (double)(NROWS * MDIM));
            out[4] = (float)(D / C);
        }
    }
}

extern "C" void kernel_launch(void* const* d_in, const int* in_sizes, int n_in,
                              void* d_out, int out_size) {
    const float *x = 0, *cen = 0, *W1 = 0, *b1 = 0, *W2 = 0, *b2 = 0;
    const int *y = 0, *perm = 0, *tmap = 0, *traw = 0;
    int n64 = 0, n2048 = 0;
    for (int i = 0; i < n_in; i++) {
        int s = in_sizes[i];
        if      (s == NROWS*BITS)     x   = (const float*)d_in[i];
        else if (s == NROWS*NCLS)     y   = (const int*)d_in[i];
        else if (s == NCLS*BITS)      cen = (const float*)d_in[i];
        else if (s == MDIM*SUBD*HID)  W1  = (const float*)d_in[i];
        else if (s == MDIM*HID*HID)   W2  = (const float*)d_in[i];
        else if (s == MDIM*HID) { if (n2048++ == 0) b1 = (const float*)d_in[i]; else b2 = (const float*)d_in[i]; }
        else if (s == BITS) {
            if (n64 == 0)      perm = (const int*)d_in[i];
            else if (n64 == 1) tmap = (const int*)d_in[i];
            else               traw = (const int*)d_in[i];
            n64++;
        }
    }
    cudaFuncSetAttribute(k_mma, cudaFuncAttributeMaxDynamicSharedMemorySize, SMEM_BYTES);
    k_init<<<1, 128>>>(cen, perm);
    k_prep<<<2048, 256>>>(W2);
    k_rows<<<4096, 256>>>(x, y, perm, tmap, traw);
    k_mma<<<dim3(NTX, MDIM, 2), 512, SMEM_BYTES>>>(W1, b1, b2);
    k_final<<<1, 256>>>((float*)d_out);
}